// round 16
// baseline (speedup 1.0000x reference)
#include <cuda_runtime.h>

#define NB1    131073   // num_bonds + 1 (sentinel row)
#define NATOMS 65536
#define NMOLS  4096
#define DH     300
#define NPD    320      // padded N (= NT * 2)
#define KI     147      // concat_fdim
#define KO     433      // atom_fdim + d_hidden
#define AFD    133
#define GFD    2048
#define RT     16       // rows per CTA tile
#define ASTRIDE 20      // transposed A-tile row stride (floats): 80B, 16B-aligned
#define NT     160      // threads per GEMM block; 2 cols/thread covers 320 >= 300

typedef unsigned long long u64;

__device__ __forceinline__ u64 pack2(float x) {
    u64 r; asm("mov.b64 %0, {%1, %1};" : "=l"(r) : "f"(x)); return r;
}
__device__ __forceinline__ void unpack2(u64 v, float& x, float& y) {
    asm("mov.b64 {%0, %1}, %2;" : "=f"(x), "=f"(y) : "l"(v));
}
__device__ __forceinline__ u64 fma2(u64 a, u64 b, u64 c) {
    u64 d; asm("fma.rn.f32x2 %0, %1, %2, %3;" : "=l"(d) : "l"(a), "l"(b), "l"(c)); return d;
}

// -------- scratch (static device globals; no allocation) --------
__device__ float g_inp[(size_t)NB1 * DH];   // pre-relu initial messages
__device__ float g_h0 [(size_t)NB1 * DH];   // h ping
__device__ float g_h1 [(size_t)NB1 * DH];   // h pong
__device__ float g_ah [(size_t)NATOMS * DH];// atoms_hidden
__device__ float g_Wti[KI * NPD];           // W_i^T padded [k][n]
__device__ float g_Wth[DH * NPD];           // W_h^T padded
__device__ float g_Wto[KO * NPD];           // W_o^T padded + col permute

// -------- weight prep: Wt[k*NPD+n] = W[n*K + j(k)] --------
__global__ void k_wprep(const float* __restrict__ W, int which, int K) {
    int idx = blockIdx.x * blockDim.x + threadIdx.x;
    if (idx >= K * NPD) return;
    int k = idx / NPD, n = idx - k * NPD;
    float v = 0.f;
    if (n < DH) {
        int j = k;
        if (which == 2) j = (k < DH) ? (AFD + k) : (k - DH);  // [msg | atom_feat] layout
        v = W[n * K + j];
    }
    float* Wt = (which == 0) ? g_Wti : (which == 1) ? g_Wth : g_Wto;
    Wt[idx] = v;
}

// -------- GEMM core: 16 rows (8 f32x2 pairs) x 2 cols/thread, K steps --------
// AsT: transposed A tile in smem, AsT[k*ASTRIDE + r], 16B-aligned rows.
template<int K>
__device__ __forceinline__ void gemm_core(const float* AsT, const float* __restrict__ Wt,
                                          int c0, int c1, u64 acc0[8], u64 acc1[8]) {
#pragma unroll
    for (int j = 0; j < 8; j++) { acc0[j] = 0ull; acc1[j] = 0ull; }
    const float* Wp = Wt;
#pragma unroll 4
    for (int k = 0; k < K; k++) {
        u64 ww0 = pack2(__ldg(Wp + c0));
        u64 ww1 = pack2(__ldg(Wp + c1));
        Wp += NPD;
        const ulonglong2* Ap = (const ulonglong2*)(AsT + k * ASTRIDE);
#pragma unroll
        for (int j = 0; j < 4; j++) {
            ulonglong2 a = Ap[j];            // LDS.128 broadcast: rows (4j..4j+3)
            acc0[2 * j]     = fma2(a.x, ww0, acc0[2 * j]);
            acc1[2 * j]     = fma2(a.x, ww1, acc1[2 * j]);
            acc0[2 * j + 1] = fma2(a.y, ww0, acc0[2 * j + 1]);
            acc1[2 * j + 1] = fma2(a.y, ww1, acc1[2 * j + 1]);
        }
    }
}

// -------- kernel 1: inp = f @ W_i^T ; h0 = relu(inp) --------
__global__ void __launch_bounds__(NT, 6) k_init(const float* __restrict__ f) {
    __shared__ __align__(16) float AsT[KI * ASTRIDE];
    int row0 = blockIdx.x * RT;
    int tid = threadIdx.x;
    for (int i = tid; i < RT * KI; i += NT) {
        int r = i / KI, k = i - r * KI;
        int row = row0 + r;
        AsT[k * ASTRIDE + r] = (row < NB1) ? f[(size_t)row * KI + k] : 0.f;
    }
    __syncthreads();

    u64 acc0[8], acc1[8];
    int c0 = tid, c1 = tid + NT;
    gemm_core<KI>(AsT, g_Wti, c0, c1, acc0, acc1);

    bool has1 = (c1 < DH);
#pragma unroll
    for (int j = 0; j < 8; j++) {
        float v0a, v0b, v1a, v1b;
        unpack2(acc0[j], v0a, v0b);
        unpack2(acc1[j], v1a, v1b);
        int ra = row0 + 2 * j, rb = ra + 1;
        if (ra < NB1) {
            float* ip = g_inp + (size_t)ra * DH;
            float* hp = g_h0  + (size_t)ra * DH;
            ip[c0] = v0a; hp[c0] = fmaxf(v0a, 0.f);
            if (has1) { ip[c1] = v1a; hp[c1] = fmaxf(v1a, 0.f); }
        }
        if (rb < NB1) {
            float* ip = g_inp + (size_t)rb * DH;
            float* hp = g_h0  + (size_t)rb * DH;
            ip[c0] = v0b; hp[c0] = fmaxf(v0b, 0.f);
            if (has1) { ip[c1] = v1b; hp[c1] = fmaxf(v1b, 0.f); }
        }
    }
}

// -------- gather-sum of 4 hidden rows into transposed smem tile --------
// first 64 threads: 4 per row, float4 chunks -> AsT[k..k+3][r]
__device__ __forceinline__ void gather_rows(const int* __restrict__ idx4,
                                            const float* __restrict__ h_old,
                                            float* AsT, int row0, int nrows_valid,
                                            int tid) {
    if (tid >= RT * 4) return;
    int r = tid >> 2, l = tid & 3;
    int row = row0 + r;
    int i0 = -1, i1 = -1, i2 = -1, i3 = -1;
    if (r < nrows_valid) {
        const int* mp = idx4 + (size_t)row * 4;
        i0 = mp[0]; i1 = mp[1]; i2 = mp[2]; i3 = mp[3];
    }
    const float4* H = (const float4*)h_old;
    for (int k4 = l; k4 < 75; k4 += 4) {
        float4 a = make_float4(0.f, 0.f, 0.f, 0.f);
        if (i0 >= 0) { float4 v = H[(size_t)i0 * 75 + k4]; a.x += v.x; a.y += v.y; a.z += v.z; a.w += v.w; }
        if (i1 >= 0) { float4 v = H[(size_t)i1 * 75 + k4]; a.x += v.x; a.y += v.y; a.z += v.z; a.w += v.w; }
        if (i2 >= 0) { float4 v = H[(size_t)i2 * 75 + k4]; a.x += v.x; a.y += v.y; a.z += v.z; a.w += v.w; }
        if (i3 >= 0) { float4 v = H[(size_t)i3 * 75 + k4]; a.x += v.x; a.y += v.y; a.z += v.z; a.w += v.w; }
        float* dst = AsT + (4 * k4) * ASTRIDE + r;
        dst[0 * ASTRIDE] = a.x;
        dst[1 * ASTRIDE] = a.y;
        dst[2 * ASTRIDE] = a.z;
        dst[3 * ASTRIDE] = a.w;
    }
}

// -------- kernel 2: h_new = relu(inp + (sum_j h_old[map[b,j]]) @ W_h^T) --------
__global__ void __launch_bounds__(NT, 6) k_mp(const int* __restrict__ mapping, int fwd) {
    const float* __restrict__ h_old = fwd ? g_h0 : g_h1;
    float* __restrict__ h_new       = fwd ? g_h1 : g_h0;

    __shared__ __align__(16) float AsT[DH * ASTRIDE];
    int row0 = blockIdx.x * RT;
    int tid = threadIdx.x;
    int nvalid = NB1 - row0; if (nvalid > RT) nvalid = RT;
    gather_rows(mapping, h_old, AsT, row0, nvalid, tid);
    __syncthreads();

    u64 acc0[8], acc1[8];
    int c0 = tid, c1 = tid + NT;
    gemm_core<DH>(AsT, g_Wth, c0, c1, acc0, acc1);

    bool has1 = (c1 < DH);
#pragma unroll
    for (int j = 0; j < 8; j++) {
        float v0a, v0b, v1a, v1b;
        unpack2(acc0[j], v0a, v0b);
        unpack2(acc1[j], v1a, v1b);
        int ra = row0 + 2 * j, rb = ra + 1;
        if (ra < NB1) {
            const float* ip = g_inp + (size_t)ra * DH;
            float* hp = h_new + (size_t)ra * DH;
            hp[c0] = fmaxf(ip[c0] + v0a, 0.f);
            if (has1) hp[c1] = fmaxf(ip[c1] + v1a, 0.f);
        }
        if (rb < NB1) {
            const float* ip = g_inp + (size_t)rb * DH;
            float* hp = h_new + (size_t)rb * DH;
            hp[c0] = fmaxf(ip[c0] + v0b, 0.f);
            if (has1) hp[c1] = fmaxf(ip[c1] + v1b, 0.f);
        }
    }
}

// -------- kernel 3: atoms_hidden = relu([msg | atom_feat] @ Wo^T + b_o) --------
__global__ void __launch_bounds__(NT, 6) k_atom(const float* __restrict__ af,
                                                const int* __restrict__ a2b,
                                                const float* __restrict__ b_o) {
    __shared__ __align__(16) float AsT[KO * ASTRIDE];  // ~34.6 KB
    int row0 = blockIdx.x * RT;
    int tid = threadIdx.x;
    for (int i = tid; i < RT * AFD; i += NT) {
        int r = i / AFD, k = i - r * AFD;
        AsT[(DH + k) * ASTRIDE + r] = af[(size_t)(row0 + r) * AFD + k];
    }
    gather_rows(a2b, g_h0, AsT, row0, RT, tid);  // final h after 2 mp steps
    __syncthreads();

    u64 acc0[8], acc1[8];
    int c0 = tid, c1 = tid + NT;
    gemm_core<KO>(AsT, g_Wto, c0, c1, acc0, acc1);

    bool has1 = (c1 < DH);
    float b0 = b_o[c0], b1 = has1 ? b_o[c1] : 0.f;
#pragma unroll
    for (int j = 0; j < 8; j++) {
        float v0a, v0b, v1a, v1b;
        unpack2(acc0[j], v0a, v0b);
        unpack2(acc1[j], v1a, v1b);
        float* opa = g_ah + (size_t)(row0 + 2 * j) * DH;
        float* opb = opa + DH;
        opa[c0] = fmaxf(v0a + b0, 0.f);
        if (has1) opa[c1] = fmaxf(v1a + b1, 0.f);
        opb[c0] = fmaxf(v0b + b0, 0.f);
        if (has1) opb[c1] = fmaxf(v1b + b1, 0.f);
    }
}

// -------- kernel 4: per-molecule mean over 16 atoms + concat globals --------
__global__ void k_read(const float* __restrict__ gf, float* __restrict__ out) {
    int m = blockIdx.x;
    int tid = threadIdx.x;
    const float* base = g_ah + (size_t)m * 16 * DH;
    for (int c = tid; c < DH; c += 256) {
        float s = 0.f;
#pragma unroll
        for (int a = 0; a < 16; a++) s += base[a * DH + c];
        out[(size_t)m * (DH + GFD) + c] = s * (1.f / 16.f);
    }
    for (int c = tid; c < GFD; c += 256)
        out[(size_t)m * (DH + GFD) + DH + c] = gf[(size_t)m * GFD + c];
}

extern "C" void kernel_launch(void* const* d_in, const int* in_sizes, int n_in,
                              void* d_out, int out_size) {
    (void)in_sizes; (void)n_in; (void)out_size;
    const float* af   = (const float*)d_in[0];  // [65536,133]
    const float* fini = (const float*)d_in[1];  // [131073,147]
    const int*   a2b  = (const int*)  d_in[2];  // [65536,4]
    const int*   mapv = (const int*)  d_in[3];  // [131073,4]
    const float* gf   = (const float*)d_in[4];  // [4096,2048]
    const float* W_i  = (const float*)d_in[5];  // [300,147]
    const float* W_h  = (const float*)d_in[6];  // [300,300]
    const float* W_o  = (const float*)d_in[7];  // [300,433]
    const float* b_o  = (const float*)d_in[8];  // [300]
    float* out = (float*)d_out;

    k_wprep<<<(KI * NPD + 255) / 256, 256>>>(W_i, 0, KI);
    k_wprep<<<(DH * NPD + 255) / 256, 256>>>(W_h, 1, DH);
    k_wprep<<<(KO * NPD + 255) / 256, 256>>>(W_o, 2, KO);

    int gbonds = (NB1 + RT - 1) / RT;   // 8193
    k_init<<<gbonds, NT>>>(fini);
    k_mp<<<gbonds, NT>>>(mapv, 1);      // h0 -> h1
    k_mp<<<gbonds, NT>>>(mapv, 0);      // h1 -> h0
    k_atom<<<NATOMS / RT, NT>>>(af, a2b, b_o);
    k_read<<<NMOLS, 256>>>(gf, out);
}

// round 17
// speedup vs baseline: 1.1512x; 1.1512x over previous
#include <cuda_runtime.h>

#define NB1    131073   // num_bonds + 1 (sentinel row)
#define NATOMS 65536
#define NMOLS  4096
#define DH     300
#define NPD    320      // padded N
#define KI     147      // concat_fdim
#define KO     433      // atom_fdim + d_hidden
#define AFD    133
#define GFD    2048
#define ASTRIDE 36      // transposed A-tile row stride (floats): 144B, 16B-aligned

typedef unsigned long long u64;

__device__ __forceinline__ u64 pack2(float x) {
    u64 r; asm("mov.b64 %0, {%1, %1};" : "=l"(r) : "f"(x)); return r;
}
__device__ __forceinline__ void unpack2(u64 v, float& x, float& y) {
    asm("mov.b64 {%0, %1}, %2;" : "=f"(x), "=f"(y) : "l"(v));
}
__device__ __forceinline__ u64 fma2(u64 a, u64 b, u64 c) {
    u64 d; asm("fma.rn.f32x2 %0, %1, %2, %3;" : "=l"(d) : "l"(a), "l"(b), "l"(c)); return d;
}

// -------- scratch (static device globals; no allocation) --------
__device__ float g_inp[(size_t)NB1 * DH];   // pre-relu initial messages
__device__ float g_h0 [(size_t)NB1 * DH];   // h ping
__device__ float g_h1 [(size_t)NB1 * DH];   // h pong
__device__ float g_ah [(size_t)NATOMS * DH];// atoms_hidden
__device__ float g_Wti[KI * NPD];           // W_i^T padded [k][n]
__device__ float g_Wth[DH * NPD];           // W_h^T padded
__device__ float g_Wto[KO * NPD];           // W_o^T padded + col permute

// -------- weight prep: Wt[k*NPD+n] = W[n*K + j(k)] --------
__global__ void k_wprep(const float* __restrict__ W, int which, int K) {
    int idx = blockIdx.x * blockDim.x + threadIdx.x;
    if (idx >= K * NPD) return;
    int k = idx / NPD, n = idx - k * NPD;
    float v = 0.f;
    if (n < DH) {
        int j = k;
        if (which == 2) j = (k < DH) ? (AFD + k) : (k - DH);  // [msg | atom_feat] layout
        v = W[n * K + j];
    }
    float* Wt = (which == 0) ? g_Wti : (which == 1) ? g_Wth : g_Wto;
    Wt[idx] = v;
}

// ======== config A (k_init): 160 threads, 2 cols/thread, 32-row tile ========
template<int K>
__device__ __forceinline__ void gemm_core2(const float* AsT, const float* __restrict__ Wt,
                                           int c0, int c1, u64 acc0[16], u64 acc1[16]) {
#pragma unroll
    for (int j = 0; j < 16; j++) { acc0[j] = 0ull; acc1[j] = 0ull; }
    const float* Wp = Wt;
#pragma unroll 2
    for (int k = 0; k < K; k++) {
        u64 ww0 = pack2(__ldg(Wp + c0));
        u64 ww1 = pack2(__ldg(Wp + c1));
        Wp += NPD;
        const ulonglong2* Ap = (const ulonglong2*)(AsT + k * ASTRIDE);
#pragma unroll
        for (int j = 0; j < 8; j++) {
            ulonglong2 a = Ap[j];            // LDS.128 broadcast: rows (4j..4j+3)
            acc0[2 * j]     = fma2(a.x, ww0, acc0[2 * j]);
            acc1[2 * j]     = fma2(a.x, ww1, acc1[2 * j]);
            acc0[2 * j + 1] = fma2(a.y, ww0, acc0[2 * j + 1]);
            acc1[2 * j + 1] = fma2(a.y, ww1, acc1[2 * j + 1]);
        }
    }
}

__global__ void __launch_bounds__(160, 4) k_init(const float* __restrict__ f) {
    __shared__ __align__(16) float AsT[KI * ASTRIDE];
    int row0 = blockIdx.x * 32;
    int tid = threadIdx.x;
    for (int i = tid; i < 32 * KI; i += 160) {
        int r = i / KI, k = i - r * KI;
        int row = row0 + r;
        AsT[k * ASTRIDE + r] = (row < NB1) ? f[(size_t)row * KI + k] : 0.f;
    }
    __syncthreads();

    u64 acc0[16], acc1[16];
    int c0 = tid, c1 = tid + 160;
    gemm_core2<KI>(AsT, g_Wti, c0, c1, acc0, acc1);

    bool has1 = (c1 < DH);
#pragma unroll
    for (int j = 0; j < 16; j++) {
        float v0a, v0b, v1a, v1b;
        unpack2(acc0[j], v0a, v0b);
        unpack2(acc1[j], v1a, v1b);
        int ra = row0 + 2 * j, rb = ra + 1;
        if (ra < NB1) {
            float* ip = g_inp + (size_t)ra * DH;
            float* hp = g_h0  + (size_t)ra * DH;
            ip[c0] = v0a; hp[c0] = fmaxf(v0a, 0.f);
            if (has1) { ip[c1] = v1a; hp[c1] = fmaxf(v1a, 0.f); }
        }
        if (rb < NB1) {
            float* ip = g_inp + (size_t)rb * DH;
            float* hp = g_h0  + (size_t)rb * DH;
            ip[c0] = v0b; hp[c0] = fmaxf(v0b, 0.f);
            if (has1) { ip[c1] = v1b; hp[c1] = fmaxf(v1b, 0.f); }
        }
    }
}

// ======== config B (k_mp, k_atom): 320 threads, 1 col/thread, 32-row tile ====
template<int K>
__device__ __forceinline__ void gemm_core1(const float* AsT, const float* __restrict__ Wt,
                                           int c, u64 acc[16]) {
#pragma unroll
    for (int j = 0; j < 16; j++) acc[j] = 0ull;
    const float* Wp = Wt + c;
#pragma unroll 4
    for (int k = 0; k < K; k++) {
        u64 ww = pack2(__ldg(Wp));
        Wp += NPD;
        const ulonglong2* Ap = (const ulonglong2*)(AsT + k * ASTRIDE);
#pragma unroll
        for (int j = 0; j < 8; j++) {
            ulonglong2 a = Ap[j];            // LDS.128 broadcast: rows (4j..4j+3)
            acc[2 * j]     = fma2(a.x, ww, acc[2 * j]);
            acc[2 * j + 1] = fma2(a.y, ww, acc[2 * j + 1]);
        }
    }
}

// -------- gather-sum of 4 hidden rows into transposed smem tile --------
// 256 threads: 8 per row, float4 chunks -> AsT[k..k+3][r]
__device__ __forceinline__ void gather_rows(const int* __restrict__ idx4,
                                            const float* __restrict__ h_old,
                                            float* AsT, int row0, int nrows_valid,
                                            int tid) {
    if (tid >= 256) return;
    int r = tid >> 3, l = tid & 7;
    int row = row0 + r;
    int i0 = -1, i1 = -1, i2 = -1, i3 = -1;
    if (r < nrows_valid) {
        const int* mp = idx4 + (size_t)row * 4;
        i0 = mp[0]; i1 = mp[1]; i2 = mp[2]; i3 = mp[3];
    }
    const float4* H = (const float4*)h_old;
    for (int k4 = l; k4 < 75; k4 += 8) {
        float4 a = make_float4(0.f, 0.f, 0.f, 0.f);
        if (i0 >= 0) { float4 v = H[(size_t)i0 * 75 + k4]; a.x += v.x; a.y += v.y; a.z += v.z; a.w += v.w; }
        if (i1 >= 0) { float4 v = H[(size_t)i1 * 75 + k4]; a.x += v.x; a.y += v.y; a.z += v.z; a.w += v.w; }
        if (i2 >= 0) { float4 v = H[(size_t)i2 * 75 + k4]; a.x += v.x; a.y += v.y; a.z += v.z; a.w += v.w; }
        if (i3 >= 0) { float4 v = H[(size_t)i3 * 75 + k4]; a.x += v.x; a.y += v.y; a.z += v.z; a.w += v.w; }
        float* dst = AsT + (4 * k4) * ASTRIDE + r;
        dst[0 * ASTRIDE] = a.x;
        dst[1 * ASTRIDE] = a.y;
        dst[2 * ASTRIDE] = a.z;
        dst[3 * ASTRIDE] = a.w;
    }
}

// -------- kernel 2: h_new = relu(inp + (sum_j h_old[map[b,j]]) @ W_h^T) --------
__global__ void __launch_bounds__(320, 3) k_mp(const int* __restrict__ mapping, int fwd) {
    const float* __restrict__ h_old = fwd ? g_h0 : g_h1;
    float* __restrict__ h_new       = fwd ? g_h1 : g_h0;

    __shared__ __align__(16) float AsT[DH * ASTRIDE];
    int row0 = blockIdx.x * 32;
    int tid = threadIdx.x;
    int nvalid = NB1 - row0; if (nvalid > 32) nvalid = 32;
    gather_rows(mapping, h_old, AsT, row0, nvalid, tid);
    __syncthreads();

    u64 acc[16];
    int c = tid;
    gemm_core1<DH>(AsT, g_Wth, c, acc);

    if (c < DH) {
#pragma unroll
        for (int j = 0; j < 16; j++) {
            float va, vb;
            unpack2(acc[j], va, vb);
            int ra = row0 + 2 * j, rb = ra + 1;
            if (ra < NB1)
                h_new[(size_t)ra * DH + c] = fmaxf(g_inp[(size_t)ra * DH + c] + va, 0.f);
            if (rb < NB1)
                h_new[(size_t)rb * DH + c] = fmaxf(g_inp[(size_t)rb * DH + c] + vb, 0.f);
        }
    }
}

// -------- kernel 3: atoms_hidden = relu([msg | atom_feat] @ Wo^T + b_o) --------
__global__ void __launch_bounds__(320, 3) k_atom(const float* __restrict__ af,
                                                 const int* __restrict__ a2b,
                                                 const float* __restrict__ b_o) {
    __shared__ __align__(16) float AsT[KO * ASTRIDE];  // ~61 KB
    int row0 = blockIdx.x * 32;
    int tid = threadIdx.x;
    for (int i = tid; i < 32 * AFD; i += 320) {
        int r = i / AFD, k = i - r * AFD;
        AsT[(DH + k) * ASTRIDE + r] = af[(size_t)(row0 + r) * AFD + k];
    }
    gather_rows(a2b, g_h0, AsT, row0, 32, tid);  // final h after 2 mp steps
    __syncthreads();

    u64 acc[16];
    int c = tid;
    gemm_core1<KO>(AsT, g_Wto, c, acc);

    if (c < DH) {
        float b = b_o[c];
#pragma unroll
        for (int j = 0; j < 16; j++) {
            float va, vb;
            unpack2(acc[j], va, vb);
            int ra = row0 + 2 * j;
            g_ah[(size_t)ra * DH + c]       = fmaxf(va + b, 0.f);
            g_ah[(size_t)(ra + 1) * DH + c] = fmaxf(vb + b, 0.f);
        }
    }
}

// -------- kernel 4: per-molecule mean over 16 atoms + concat globals --------
__global__ void k_read(const float* __restrict__ gf, float* __restrict__ out) {
    int m = blockIdx.x;
    int tid = threadIdx.x;
    const float* base = g_ah + (size_t)m * 16 * DH;
    for (int c = tid; c < DH; c += 256) {
        float s = 0.f;
#pragma unroll
        for (int a = 0; a < 16; a++) s += base[a * DH + c];
        out[(size_t)m * (DH + GFD) + c] = s * (1.f / 16.f);
    }
    for (int c = tid; c < GFD; c += 256)
        out[(size_t)m * (DH + GFD) + DH + c] = gf[(size_t)m * GFD + c];
}

extern "C" void kernel_launch(void* const* d_in, const int* in_sizes, int n_in,
                              void* d_out, int out_size) {
    (void)in_sizes; (void)n_in; (void)out_size;
    const float* af   = (const float*)d_in[0];  // [65536,133]
    const float* fini = (const float*)d_in[1];  // [131073,147]
    const int*   a2b  = (const int*)  d_in[2];  // [65536,4]
    const int*   mapv = (const int*)  d_in[3];  // [131073,4]
    const float* gf   = (const float*)d_in[4];  // [4096,2048]
    const float* W_i  = (const float*)d_in[5];  // [300,147]
    const float* W_h  = (const float*)d_in[6];  // [300,300]
    const float* W_o  = (const float*)d_in[7];  // [300,433]
    const float* b_o  = (const float*)d_in[8];  // [300]
    float* out = (float*)d_out;

    k_wprep<<<(KI * NPD + 255) / 256, 256>>>(W_i, 0, KI);
    k_wprep<<<(DH * NPD + 255) / 256, 256>>>(W_h, 1, DH);
    k_wprep<<<(KO * NPD + 255) / 256, 256>>>(W_o, 2, KO);

    int gbonds = (NB1 + 31) / 32;     // 4097
    k_init<<<gbonds, 160>>>(fini);
    k_mp<<<gbonds, 320>>>(mapv, 1);   // h0 -> h1
    k_mp<<<gbonds, 320>>>(mapv, 0);   // h1 -> h0
    k_atom<<<NATOMS / 32, 320>>>(af, a2b, b_o);
    k_read<<<NMOLS, 256>>>(gf, out);
}